// round 14
// baseline (speedup 1.0000x reference)
#include <cuda_runtime.h>
#include <cuda_bf16.h>
#include <cstdint>

#define BB 16
#define TT 2048
#define DD 512
#define AA 64
#define NROWS (BB*TT)

// ---------------- device scratch ----------------
__device__ __align__(16) float g_Qf[NROWS*AA];   // fp32, pre-scaled by 0.125*log2e
__device__ __align__(16) float g_Kf[NROWS*AA];   // fp32, k-cols permuted: (k,k+4) adjacent
__device__ __align__(16) __nv_bfloat16 g_WThi[128*DD];
__device__ __align__(16) __nv_bfloat16 g_WTlo[128*DD];
__device__ __align__(16) float2 g_wz[NROWS];
__device__ __align__(16) float g_l[NROWS];
__device__ __align__(16) float g_acc[NROWS];
__device__ float g_wqs[DD], g_wks[DD], g_wvs[DD];
__device__ float g_bs[3];

#define SC2F 0.18033688011112043f   // 0.125 * log2(e)

// ---------------- helpers ----------------
__device__ __forceinline__ uint32_t smem_u32(const void* p) {
    return (uint32_t)__cvta_generic_to_shared(p);
}
__device__ __forceinline__ float ex2f(float x) {
    float y; asm("ex2.approx.ftz.f32 %0, %1;" : "=f"(y) : "f"(x)); return y;
}
__device__ __forceinline__ uint32_t cvt_tf32(float f) {
    uint32_t u; asm("cvt.rna.tf32.f32 %0, %1;" : "=r"(u) : "f"(f)); return u;
}
__device__ __forceinline__ void ldsm4(uint32_t* r, uint32_t addr) {
    asm volatile("ldmatrix.sync.aligned.m8n8.x4.shared.b16 {%0,%1,%2,%3}, [%4];"
        : "=r"(r[0]), "=r"(r[1]), "=r"(r[2]), "=r"(r[3]) : "r"(addr));
}
__device__ __forceinline__ void mma16816(float* c, const uint32_t* a, const uint32_t* b) {
    asm volatile("mma.sync.aligned.m16n8k16.row.col.f32.bf16.bf16.f32 "
        "{%0,%1,%2,%3}, {%4,%5,%6,%7}, {%8,%9}, {%0,%1,%2,%3};"
        : "+f"(c[0]), "+f"(c[1]), "+f"(c[2]), "+f"(c[3])
        : "r"(a[0]), "r"(a[1]), "r"(a[2]), "r"(a[3]), "r"(b[0]), "r"(b[1]));
}
__device__ __forceinline__ void mma168tf(float* c, const uint32_t* a, uint32_t b0, uint32_t b1) {
    asm volatile("mma.sync.aligned.m16n8k8.row.col.f32.tf32.tf32.f32 "
        "{%0,%1,%2,%3}, {%4,%5,%6,%7}, {%8,%9}, {%0,%1,%2,%3};"
        : "+f"(c[0]), "+f"(c[1]), "+f"(c[2]), "+f"(c[3])
        : "r"(a[0]), "r"(a[1]), "r"(a[2]), "r"(a[3]), "r"(b0), "r"(b1));
}
#define CPA(dst, src) asm volatile("cp.async.cg.shared.global [%0], [%1], 16;" :: "r"(dst), "l"(src))
#define CPC() asm volatile("cp.async.commit_group;" ::: "memory")
#define CPW0() asm volatile("cp.async.wait_group 0;" ::: "memory")
#define CPW1() asm volatile("cp.async.wait_group 1;" ::: "memory")

// proj smem swizzle (128-byte rows)
__device__ __forceinline__ uint32_t tadr(uint32_t base, int r, int kb) {
    return base + ((((uint32_t)r << 7) | (uint32_t)kb) ^ (((uint32_t)(r & 7)) << 4));
}
__device__ __forceinline__ uint32_t pk2(__nv_bfloat16 a, __nv_bfloat16 b) {
    __nv_bfloat162 t = __halves2bfloat162(a, b);
    return *reinterpret_cast<uint32_t*>(&t);
}
__device__ __forceinline__ uint32_t pkf(float a, float b) {
    __nv_bfloat162 t = __floats2bfloat162_rn(a, b);
    return *reinterpret_cast<uint32_t*>(&t);
}

// ---------------- kernel A: zero out + l/acc partials ----------------
__global__ __launch_bounds__(512) void k_zero(float* __restrict__ out) {
    int idx = blockIdx.x * 512 + threadIdx.x;
    g_l[idx] = 0.f;
    g_acc[idx] = 0.f;
    if (blockIdx.x < 16) out[blockIdx.x * 512 + threadIdx.x] = 0.f;
}

// ---------------- kernel 0: W col sums + transpose ----------------
__global__ __launch_bounds__(256) void k_wsum(const float* __restrict__ Wq, const float* __restrict__ Wk,
                       const float* __restrict__ Wv,
                       const float* __restrict__ bq, const float* __restrict__ bk,
                       const float* __restrict__ bv) {
    int wid = threadIdx.x >> 5, lane = threadIdx.x & 31;
    int d = blockIdx.x * 8 + wid;

    float wq0 = Wq[d*AA + lane],      wq1 = Wq[d*AA + 32 + lane];
    float wk0 = Wk[d*AA + lane],      wk1 = Wk[d*AA + 32 + lane];
    float wv0 = Wv[d*AA + lane],      wv1 = Wv[d*AA + 32 + lane];

    float sq = wq0 + wq1, sk = wk0 + wk1, sv = wv0 + wv1;
    #pragma unroll
    for (int off = 16; off > 0; off >>= 1) {
        sq += __shfl_xor_sync(0xffffffffu, sq, off);
        sk += __shfl_xor_sync(0xffffffffu, sk, off);
        sv += __shfl_xor_sync(0xffffffffu, sv, off);
    }
    if (lane == 0) { g_wqs[d] = sq; g_wks[d] = sk; g_wvs[d] = sv; }

    #pragma unroll
    for (int half = 0; half < 2; half++) {
        int a = lane + half * 32;
        float vq = half ? wq1 : wq0;
        float vk = half ? wk1 : wk0;
        __nv_bfloat16 hq = __float2bfloat16_rn(vq);
        __nv_bfloat16 hk = __float2bfloat16_rn(vk);
        g_WThi[a*DD + d]        = hq;
        g_WTlo[a*DD + d]        = __float2bfloat16_rn(vq - __bfloat162float(hq));
        g_WThi[(64 + a)*DD + d] = hk;
        g_WTlo[(64 + a)*DD + d] = __float2bfloat16_rn(vk - __bfloat162float(hk));
    }

    if (blockIdx.x == 0 && threadIdx.x < 3) {
        const float* bb = (threadIdx.x == 0) ? bq : (threadIdx.x == 1) ? bk : bv;
        float s = 0.f;
        #pragma unroll 8
        for (int a = 0; a < AA; a++) s += bb[a];
        g_bs[threadIdx.x] = s;
    }
}

// ---------------- kernel 1: HMMA Q,K projection (split bf16) + mask rowsums ----------------
#define PJ_A 0
#define PJ_B 16384
#define PJ_SMEM (16384 + 32768)

__global__ __launch_bounds__(256) void k_proj_mma(const float* __restrict__ inp,
                                                  const float* __restrict__ bq,
                                                  const float* __restrict__ bk) {
    extern __shared__ char sm[];
    uint32_t smb = smem_u32(sm);
    int tid = threadIdx.x;
    int lane = tid & 31;
    int wid = tid >> 5;
    int m0 = (wid >> 2) * 32;
    int wn = wid & 3;
    int n0 = wn * 32;
    int rowbase = blockIdx.x * 64;

    int ar = tid >> 2, aq = tid & 3;
    int bn = tid >> 1, bh = tid & 1;

    float C[2][4][4];
    #pragma unroll
    for (int a = 0; a < 2; a++)
        #pragma unroll
        for (int b = 0; b < 4; b++)
            #pragma unroll
            for (int c = 0; c < 4; c++) C[a][b][c] = 0.f;
    float dq = 0.f, dk = 0.f, dv = 0.f;

    const float* arow_p = inp + (size_t)(rowbase + ar) * DD + aq * 8;
    const char* bsrc_h = (const char*)g_WThi + (size_t)bn * 1024 + bh * 32;
    const char* bsrc_l = (const char*)g_WTlo + (size_t)bn * 1024 + bh * 32;

    float4 xa = *(const float4*)(arow_p);
    float4 xb = *(const float4*)(arow_p + 4);
    {
        uint32_t bb = smb + PJ_B;
        CPA(tadr(bb, bn, bh*32),           bsrc_h);
        CPA(tadr(bb, bn, bh*32 + 16),      bsrc_h + 16);
        CPA(tadr(bb, bn, 64 + bh*32),      bsrc_l);
        CPA(tadr(bb, bn, 64 + bh*32 + 16), bsrc_l + 16);
        CPC();
    }

    for (int kc = 0; kc < 16; kc++) {
        int buf = kc & 1;
        {
            int koff = kc * 32 + aq * 8;
            const float4* wq4 = (const float4*)(g_wqs + koff);
            const float4* wk4 = (const float4*)(g_wks + koff);
            const float4* wv4 = (const float4*)(g_wvs + koff);
            float4 a0 = wq4[0], a1 = wq4[1];
            dq += xa.x*a0.x + xa.y*a0.y + xa.z*a0.z + xa.w*a0.w
                + xb.x*a1.x + xb.y*a1.y + xb.z*a1.z + xb.w*a1.w;
            float4 b0 = wk4[0], b1 = wk4[1];
            dk += xa.x*b0.x + xa.y*b0.y + xa.z*b0.z + xa.w*b0.w
                + xb.x*b1.x + xb.y*b1.y + xb.z*b1.z + xb.w*b1.w;
            float4 c0 = wv4[0], c1 = wv4[1];
            dv += xa.x*c0.x + xa.y*c0.y + xa.z*c0.z + xa.w*c0.w
                + xb.x*c1.x + xb.y*c1.y + xb.z*c1.z + xb.w*c1.w;
        }
        {
            __nv_bfloat16 h0 = __float2bfloat16_rn(xa.x), h1 = __float2bfloat16_rn(xa.y);
            __nv_bfloat16 h2 = __float2bfloat16_rn(xa.z), h3 = __float2bfloat16_rn(xa.w);
            __nv_bfloat16 h4 = __float2bfloat16_rn(xb.x), h5 = __float2bfloat16_rn(xb.y);
            __nv_bfloat16 h6 = __float2bfloat16_rn(xb.z), h7 = __float2bfloat16_rn(xb.w);
            uint4 hw, lw;
            hw.x = pk2(h0, h1); hw.y = pk2(h2, h3); hw.z = pk2(h4, h5); hw.w = pk2(h6, h7);
            lw.x = pkf(xa.x - __bfloat162float(h0), xa.y - __bfloat162float(h1));
            lw.y = pkf(xa.z - __bfloat162float(h2), xa.w - __bfloat162float(h3));
            lw.z = pkf(xb.x - __bfloat162float(h4), xb.y - __bfloat162float(h5));
            lw.w = pkf(xb.z - __bfloat162float(h6), xb.w - __bfloat162float(h7));
            uint32_t abase = PJ_A + buf * 8192;
            *(uint4*)(sm + tadr(abase, ar, aq*16))      = hw;
            *(uint4*)(sm + tadr(abase, ar, 64 + aq*16)) = lw;
        }
        if (kc < 15) {
            xa = *(const float4*)(arow_p + (kc + 1) * 32);
            xb = *(const float4*)(arow_p + (kc + 1) * 32 + 4);
        }
        if (kc < 15) {
            uint32_t bb = smb + PJ_B + (buf ^ 1) * 16384;
            const char* bh_p = bsrc_h + (kc + 1) * 64;
            const char* bl_p = bsrc_l + (kc + 1) * 64;
            CPA(tadr(bb, bn, bh*32),           bh_p);
            CPA(tadr(bb, bn, bh*32 + 16),      bh_p + 16);
            CPA(tadr(bb, bn, 64 + bh*32),      bl_p);
            CPA(tadr(bb, bn, 64 + bh*32 + 16), bl_p + 16);
            CPC();
            CPW1();
        } else {
            CPW0();
        }
        __syncthreads();

        uint32_t Ab = smb + PJ_A + buf * 8192;
        uint32_t Bb = smb + PJ_B + buf * 16384;
        #pragma unroll
        for (int ks = 0; ks < 2; ks++) {
            int akb = ks*32 + ((lane >> 4) << 4);
            int arw = m0 + (lane & 15);
            uint32_t ahi[2][4], alo[2][4];
            ldsm4(ahi[0], tadr(Ab, arw,      akb));
            ldsm4(ahi[1], tadr(Ab, arw + 16, akb));
            ldsm4(alo[0], tadr(Ab, arw,      akb + 64));
            ldsm4(alo[1], tadr(Ab, arw + 16, akb + 64));
            int brow = (lane & 7) | ((lane >> 4) << 3);
            int bkb = ks*32 + ((lane & 8) << 1);
            uint32_t bhi[4][2], blo[4][2];
            ldsm4(&bhi[0][0], tadr(Bb, n0 + brow,      bkb));
            ldsm4(&bhi[2][0], tadr(Bb, n0 + 16 + brow, bkb));
            ldsm4(&blo[0][0], tadr(Bb, n0 + brow,      bkb + 64));
            ldsm4(&blo[2][0], tadr(Bb, n0 + 16 + brow, bkb + 64));
            // split-flavor outermost: same-accumulator distance 8 (was 1)
            #pragma unroll
            for (int p = 0; p < 3; p++) {
                #pragma unroll
                for (int mf = 0; mf < 2; mf++)
                    #pragma unroll
                    for (int nf = 0; nf < 4; nf++)
                        mma16816(C[mf][nf],
                                 (p == 2) ? alo[mf] : ahi[mf],
                                 (p == 1) ? blo[nf] : bhi[nf]);
            }
        }
    }

    // ---- finalize mask rowsums ----
    dq += __shfl_xor_sync(0xffffffffu, dq, 1);
    dq += __shfl_xor_sync(0xffffffffu, dq, 2);
    dk += __shfl_xor_sync(0xffffffffu, dk, 1);
    dk += __shfl_xor_sync(0xffffffffu, dk, 2);
    dv += __shfl_xor_sync(0xffffffffu, dv, 1);
    dv += __shfl_xor_sync(0xffffffffu, dv, 2);
    if (aq == 0) {
        float qs = dq + g_bs[0];
        float ks_ = dk + g_bs[1];
        float vs = dv + g_bs[2];
        g_wz[rowbase + ar] = make_float2((qs != 0.f) ? vs : 0.f,
                                         (ks_ == 0.f) ? 1.f : 0.f);
    }

    // ---- epilogue: Q fp32 (pre-scaled), K fp32 with column pair-permutation ----
    #pragma unroll
    for (int mf = 0; mf < 2; mf++) {
        int r0 = rowbase + m0 + mf*16 + (lane >> 2);
        #pragma unroll
        for (int nf = 0; nf < 4; nf++) {
            if (wn < 2) {
                int c = wn*32 + nf*8 + (lane & 3)*2;
                float b0 = __ldg(bq + c), b1 = __ldg(bq + c + 1);
                float2 v01 = make_float2((C[mf][nf][0] + b0) * SC2F, (C[mf][nf][1] + b1) * SC2F);
                float2 v23 = make_float2((C[mf][nf][2] + b0) * SC2F, (C[mf][nf][3] + b1) * SC2F);
                *(float2*)(g_Qf + (size_t)r0*AA + c)     = v01;
                *(float2*)(g_Qf + (size_t)(r0+8)*AA + c) = v23;
            } else {
                int c = (wn-2)*32 + nf*8 + (lane & 3)*2;
                float b0 = __ldg(bk + c), b1 = __ldg(bk + c + 1);
                // permute within 8-group: k -> ((k&3)<<1)|(k>>2)
                int cg = c & ~7, e = c & 7;
                int p0 = cg | (((e & 3) << 1) | (e >> 2));
                int p1 = cg | ((((e+1) & 3) << 1) | ((e+1) >> 2));
                g_Kf[(size_t)r0*AA + p0]     = C[mf][nf][0] + b0;
                g_Kf[(size_t)r0*AA + p1]     = C[mf][nf][1] + b1;
                g_Kf[(size_t)(r0+8)*AA + p0] = C[mf][nf][2] + b0;
                g_Kf[(size_t)(r0+8)*AA + p1] = C[mf][nf][3] + b1;
            }
        }
    }
}

// ---------------- kernel 2: tf32 flash attention, vectorized B + split accumulators ----------------
// grid (16 q-tiles, BB, 4 kv-splits); CTA 128 thr; 128q/CTA, 32q/warp; 8 key tiles of 64.
// K smem: 64 rows x 256B, 32B-chunk XOR swizzle; B frag = 1 LDS.64 per ks (conflict-free).
#define AT_KBUF 16384              // 64 x 256B
#define AT_K    0                  // 2 bufs
#define AT_WS   (2 * AT_KBUF)      // 2 x 512B
#define AT_SMEM (2 * AT_KBUF + 1024)
#define NKT_SPLIT 8

__global__ __launch_bounds__(128, 3) void k_attn_mma() {
    extern __shared__ char sm[];
    uint32_t smb = smem_u32(sm);
    int tid = threadIdx.x;
    int lane = tid & 31;
    int wid = tid >> 5;
    int tig = lane & 3, g = lane >> 2;
    int b = blockIdx.y;
    int z = blockIdx.z;
    int qrow0 = b * TT + blockIdx.x * 128;
    int kbase = b * TT + z * (NKT_SPLIT * 64);
    int wq0 = wid * 32;

    int lr = tid >> 1, lh = tid & 1;     // loader: row, 128B-half

    // prime K tile 0 + wz
    {
        const char* src = (const char*)(g_Kf + (size_t)(kbase + lr) * AA) + lh * 128;
        uint32_t rbase = smb + AT_K + lr * 256;
        #pragma unroll
        for (int j = 0; j < 8; j++) {
            int byte = lh * 128 + j * 16;
            uint32_t dst = rbase + ((byte & ~31) ^ ((lr & 7) << 5)) + (byte & 31);
            CPA(dst, src + j * 16);
        }
        if (tid < 32) CPA(smb + AT_WS + tid*16, (const char*)(g_wz + kbase) + tid*16);
        CPC();
    }

    // hoist Q fragments from global (loop-invariant)
    uint32_t qf[8][2][4];
    #pragma unroll
    for (int ks = 0; ks < 8; ks++) {
        int col = ks*8 + tig;
        #pragma unroll
        for (int mf = 0; mf < 2; mf++) {
            int row = qrow0 + wq0 + mf*16 + g;
            qf[ks][mf][0] = cvt_tf32(__ldg(g_Qf + (size_t)row*AA + col));
            qf[ks][mf][1] = cvt_tf32(__ldg(g_Qf + (size_t)(row+8)*AA + col));
            qf[ks][mf][2] = cvt_tf32(__ldg(g_Qf + (size_t)row*AA + col + 4));
            qf[ks][mf][3] = cvt_tf32(__ldg(g_Qf + (size_t)(row+8)*AA + col + 4));
        }
    }

    CPW0();
    __syncthreads();

    const float KZ2 = 1.4426950408889634e-8f;
    float l[4], acc[4];
    #pragma unroll
    for (int h = 0; h < 4; h++) { l[h] = 0.f; acc[h] = 0.f; }

    const int ksord[8] = {0, 4, 1, 5, 2, 6, 3, 7};

    for (int kt = 0; kt < NKT_SPLIT; kt++) {
        int buf = kt & 1;
        if (kt + 1 < NKT_SPLIT) {
            int krow0 = kbase + (kt + 1) * 64;
            const char* src = (const char*)(g_Kf + (size_t)(krow0 + lr) * AA) + lh * 128;
            uint32_t rbase = smb + AT_K + (buf ^ 1) * AT_KBUF + lr * 256;
            #pragma unroll
            for (int j = 0; j < 8; j++) {
                int byte = lh * 128 + j * 16;
                uint32_t dst = rbase + ((byte & ~31) ^ ((lr & 7) << 5)) + (byte & 31);
                CPA(dst, src + j * 16);
            }
            if (tid < 32) CPA(smb + AT_WS + (buf ^ 1) * 512 + tid*16,
                              (const char*)(g_wz + krow0) + tid*16);
            CPC();
        }

        const char* kb = sm + AT_K + buf * AT_KBUF;
        const float2* wkp = (const float2*)(sm + AT_WS + buf * 512);

        #pragma unroll
        for (int nt = 0; nt < 8; nt++) {
            // split accumulators by ks-half: chain depth 4
            float C[2][2][4];
            #pragma unroll
            for (int mf = 0; mf < 2; mf++)
                #pragma unroll
                for (int hh = 0; hh < 2; hh++)
                    #pragma unroll
                    for (int c = 0; c < 4; c++) C[mf][hh][c] = 0.f;

            const char* bp = kb + (nt*8 + g) * 256 + tig * 8;
            #pragma unroll
            for (int i = 0; i < 8; i++) {
                int ks = ksord[i];
                int hh = ks >> 2;
                float2 bv = *(const float2*)(bp + ((ks ^ g) * 32));
                uint32_t b0 = __float_as_uint(bv.x), b1 = __float_as_uint(bv.y);
                mma168tf(C[0][hh], qf[ks][0], b0, b1);
                mma168tf(C[1][hh], qf[ks][1], b0, b1);
            }

            #pragma unroll
            for (int j2 = 0; j2 < 2; j2++) {
                int col = nt*8 + tig*2 + j2;
                float2 wk = wkp[col];
                #pragma unroll
                for (int mf = 0; mf < 2; mf++)
                    #pragma unroll
                    for (int h = 0; h < 2; h++) {
                        int ci = (h << 1) + j2;
                        float raw = C[mf][0][ci] + C[mf][1][ci];
                        float v = (wk.y != 0.f) ? KZ2 : raw;
                        float p = ex2f(v);
                        l[mf*2 + h] += p;
                        acc[mf*2 + h] += p * wk.x;
                    }
            }
        }

        if (kt + 1 < NKT_SPLIT) CPW0();
        __syncthreads();
    }

    #pragma unroll
    for (int mf = 0; mf < 2; mf++)
        #pragma unroll
        for (int h = 0; h < 2; h++) {
            float lv = l[mf*2 + h], av = acc[mf*2 + h];
            lv += __shfl_xor_sync(0xffffffffu, lv, 1);
            lv += __shfl_xor_sync(0xffffffffu, lv, 2);
            av += __shfl_xor_sync(0xffffffffu, av, 1);
            av += __shfl_xor_sync(0xffffffffu, av, 2);
            if ((lane & 3) == 0) {
                int row = qrow0 + wq0 + mf*16 + h*8 + (lane >> 2);
                atomicAdd(&g_l[row], lv);
                atomicAdd(&g_acc[row], av);
            }
        }
}

// ---------------- kernel 3: out[b,d] += sum_t inp[b,t,d] * (acc[t]/l[t]) ----------------
__global__ __launch_bounds__(128) void k_out2(const float* __restrict__ inp,
                                              float* __restrict__ out) {
    __shared__ float c_sm[64];
    int b = blockIdx.y;
    int ts = blockIdx.x;
    int td = threadIdx.x;
    if (td < 64) {
        int idx = b * TT + ts * 64 + td;
        c_sm[td] = g_acc[idx] / g_l[idx];
    }
    __syncthreads();
    const float4* ip = (const float4*)(inp + (size_t)b * TT * DD) + (size_t)(ts * 64) * 128 + td;
    float4 acc = make_float4(0.f, 0.f, 0.f, 0.f);
    #pragma unroll 8
    for (int t = 0; t < 64; t++) {
        float4 x = ip[(size_t)t * 128];
        float cv = c_sm[t];
        acc.x += x.x * cv; acc.y += x.y * cv;
        acc.z += x.z * cv; acc.w += x.w * cv;
    }
    float* op = out + b * DD + td * 4;
    atomicAdd(op + 0, acc.x);
    atomicAdd(op + 1, acc.y);
    atomicAdd(op + 2, acc.z);
    atomicAdd(op + 3, acc.w);
}

// ---------------- launch ----------------
extern "C" void kernel_launch(void* const* d_in, const int* in_sizes, int n_in,
                              void* d_out, int out_size) {
    const float* inp = (const float*)d_in[0];
    const float* Wq  = (const float*)d_in[1];
    const float* bq  = (const float*)d_in[2];
    const float* Wk  = (const float*)d_in[3];
    const float* bk  = (const float*)d_in[4];
    const float* Wv  = (const float*)d_in[5];
    const float* bv  = (const float*)d_in[6];
    float* out = (float*)d_out;

    static int inited = 0;
    if (!inited) {
        cudaFuncSetAttribute(k_proj_mma, cudaFuncAttributeMaxDynamicSharedMemorySize, PJ_SMEM);
        cudaFuncSetAttribute(k_attn_mma, cudaFuncAttributeMaxDynamicSharedMemorySize, AT_SMEM);
        inited = 1;
    }

    k_zero<<<64, 512>>>(out);                                  // launch 1
    k_wsum<<<64, 256>>>(Wq, Wk, Wv, bq, bk, bv);               // launch 2
    k_proj_mma<<<NROWS / 64, 256, PJ_SMEM>>>(inp, bq, bk);     // launch 3
    k_attn_mma<<<dim3(TT / 128, BB, 4), 128, AT_SMEM>>>();     // launch 4 (profiled)
    k_out2<<<dim3(32, BB), 128>>>(inp, out);                   // launch 5
}

// round 15
// speedup vs baseline: 1.3377x; 1.3377x over previous
#include <cuda_runtime.h>
#include <cuda_bf16.h>
#include <cuda_fp16.h>
#include <cstdint>

#define BB 16
#define TT 2048
#define DD 512
#define AA 64
#define NROWS (BB*TT)

// ---------------- device scratch ----------------
__device__ __align__(16) __half g_Qh[NROWS*AA];   // fp16, pre-scaled by 0.125*log2e
__device__ __align__(16) __half g_Kh[NROWS*AA];   // fp16
__device__ __align__(16) __nv_bfloat16 g_WThi[128*DD];
__device__ __align__(16) __nv_bfloat16 g_WTlo[128*DD];
__device__ __align__(16) float2 g_wz[NROWS];
__device__ __align__(16) float g_l[NROWS];
__device__ __align__(16) float g_acc[NROWS];
__device__ float g_wqs[DD], g_wks[DD], g_wvs[DD];
__device__ float g_bs[3];

#define SC2F 0.18033688011112043f   // 0.125 * log2(e)

// ---------------- helpers ----------------
__device__ __forceinline__ uint32_t smem_u32(const void* p) {
    return (uint32_t)__cvta_generic_to_shared(p);
}
__device__ __forceinline__ float ex2f(float x) {
    float y; asm("ex2.approx.ftz.f32 %0, %1;" : "=f"(y) : "f"(x)); return y;
}
__device__ __forceinline__ void ldsm4(uint32_t* r, uint32_t addr) {
    asm volatile("ldmatrix.sync.aligned.m8n8.x4.shared.b16 {%0,%1,%2,%3}, [%4];"
        : "=r"(r[0]), "=r"(r[1]), "=r"(r[2]), "=r"(r[3]) : "r"(addr));
}
__device__ __forceinline__ void mma16816(float* c, const uint32_t* a, const uint32_t* b) {
    asm volatile("mma.sync.aligned.m16n8k16.row.col.f32.bf16.bf16.f32 "
        "{%0,%1,%2,%3}, {%4,%5,%6,%7}, {%8,%9}, {%0,%1,%2,%3};"
        : "+f"(c[0]), "+f"(c[1]), "+f"(c[2]), "+f"(c[3])
        : "r"(a[0]), "r"(a[1]), "r"(a[2]), "r"(a[3]), "r"(b[0]), "r"(b[1]));
}
__device__ __forceinline__ void mma16816h(float* c, const uint32_t* a, const uint32_t* b) {
    asm volatile("mma.sync.aligned.m16n8k16.row.col.f32.f16.f16.f32 "
        "{%0,%1,%2,%3}, {%4,%5,%6,%7}, {%8,%9}, {%0,%1,%2,%3};"
        : "+f"(c[0]), "+f"(c[1]), "+f"(c[2]), "+f"(c[3])
        : "r"(a[0]), "r"(a[1]), "r"(a[2]), "r"(a[3]), "r"(b[0]), "r"(b[1]));
}
#define CPA(dst, src) asm volatile("cp.async.cg.shared.global [%0], [%1], 16;" :: "r"(dst), "l"(src))
#define CPC() asm volatile("cp.async.commit_group;" ::: "memory")
#define CPW0() asm volatile("cp.async.wait_group 0;" ::: "memory")
#define CPW1() asm volatile("cp.async.wait_group 1;" ::: "memory")

// 128-byte rows, xor swizzle (bits 4-6) for conflict-free ldmatrix
__device__ __forceinline__ uint32_t tadr(uint32_t base, int r, int kb) {
    return base + ((((uint32_t)r << 7) | (uint32_t)kb) ^ (((uint32_t)(r & 7)) << 4));
}
__device__ __forceinline__ uint32_t pk2(__nv_bfloat16 a, __nv_bfloat16 b) {
    __nv_bfloat162 t = __halves2bfloat162(a, b);
    return *reinterpret_cast<uint32_t*>(&t);
}
__device__ __forceinline__ uint32_t pkf(float a, float b) {
    __nv_bfloat162 t = __floats2bfloat162_rn(a, b);
    return *reinterpret_cast<uint32_t*>(&t);
}
__device__ __forceinline__ uint32_t pkh(float a, float b) {
    __half2 t = __floats2half2_rn(a, b);
    return *reinterpret_cast<uint32_t*>(&t);
}

// ---------------- kernel A: zero out + l/acc partials ----------------
__global__ __launch_bounds__(512) void k_zero(float* __restrict__ out) {
    int idx = blockIdx.x * 512 + threadIdx.x;
    g_l[idx] = 0.f;
    g_acc[idx] = 0.f;
    if (blockIdx.x < 16) out[blockIdx.x * 512 + threadIdx.x] = 0.f;
}

// ---------------- kernel 0: W col sums + transpose ----------------
__global__ __launch_bounds__(256) void k_wsum(const float* __restrict__ Wq, const float* __restrict__ Wk,
                       const float* __restrict__ Wv,
                       const float* __restrict__ bq, const float* __restrict__ bk,
                       const float* __restrict__ bv) {
    int wid = threadIdx.x >> 5, lane = threadIdx.x & 31;
    int d = blockIdx.x * 8 + wid;

    float wq0 = Wq[d*AA + lane],      wq1 = Wq[d*AA + 32 + lane];
    float wk0 = Wk[d*AA + lane],      wk1 = Wk[d*AA + 32 + lane];
    float wv0 = Wv[d*AA + lane],      wv1 = Wv[d*AA + 32 + lane];

    float sq = wq0 + wq1, sk = wk0 + wk1, sv = wv0 + wv1;
    #pragma unroll
    for (int off = 16; off > 0; off >>= 1) {
        sq += __shfl_xor_sync(0xffffffffu, sq, off);
        sk += __shfl_xor_sync(0xffffffffu, sk, off);
        sv += __shfl_xor_sync(0xffffffffu, sv, off);
    }
    if (lane == 0) { g_wqs[d] = sq; g_wks[d] = sk; g_wvs[d] = sv; }

    #pragma unroll
    for (int half = 0; half < 2; half++) {
        int a = lane + half * 32;
        float vq = half ? wq1 : wq0;
        float vk = half ? wk1 : wk0;
        __nv_bfloat16 hq = __float2bfloat16_rn(vq);
        __nv_bfloat16 hk = __float2bfloat16_rn(vk);
        g_WThi[a*DD + d]        = hq;
        g_WTlo[a*DD + d]        = __float2bfloat16_rn(vq - __bfloat162float(hq));
        g_WThi[(64 + a)*DD + d] = hk;
        g_WTlo[(64 + a)*DD + d] = __float2bfloat16_rn(vk - __bfloat162float(hk));
    }

    if (blockIdx.x == 0 && threadIdx.x < 3) {
        const float* bb = (threadIdx.x == 0) ? bq : (threadIdx.x == 1) ? bk : bv;
        float s = 0.f;
        #pragma unroll 8
        for (int a = 0; a < AA; a++) s += bb[a];
        g_bs[threadIdx.x] = s;
    }
}

// ---------------- kernel 1: HMMA Q,K projection (split bf16) + mask rowsums ----------------
#define PJ_A 0
#define PJ_B 16384
#define PJ_SMEM (16384 + 32768)

__global__ __launch_bounds__(256) void k_proj_mma(const float* __restrict__ inp,
                                                  const float* __restrict__ bq,
                                                  const float* __restrict__ bk) {
    extern __shared__ char sm[];
    uint32_t smb = smem_u32(sm);
    int tid = threadIdx.x;
    int lane = tid & 31;
    int wid = tid >> 5;
    int m0 = (wid >> 2) * 32;
    int wn = wid & 3;
    int n0 = wn * 32;
    int rowbase = blockIdx.x * 64;

    int ar = tid >> 2, aq = tid & 3;
    int bn = tid >> 1, bh = tid & 1;

    float C[2][4][4];
    #pragma unroll
    for (int a = 0; a < 2; a++)
        #pragma unroll
        for (int b = 0; b < 4; b++)
            #pragma unroll
            for (int c = 0; c < 4; c++) C[a][b][c] = 0.f;
    float dq = 0.f, dk = 0.f, dv = 0.f;

    const float* arow_p = inp + (size_t)(rowbase + ar) * DD + aq * 8;
    const char* bsrc_h = (const char*)g_WThi + (size_t)bn * 1024 + bh * 32;
    const char* bsrc_l = (const char*)g_WTlo + (size_t)bn * 1024 + bh * 32;

    float4 xa = *(const float4*)(arow_p);
    float4 xb = *(const float4*)(arow_p + 4);
    {
        uint32_t bb = smb + PJ_B;
        CPA(tadr(bb, bn, bh*32),           bsrc_h);
        CPA(tadr(bb, bn, bh*32 + 16),      bsrc_h + 16);
        CPA(tadr(bb, bn, 64 + bh*32),      bsrc_l);
        CPA(tadr(bb, bn, 64 + bh*32 + 16), bsrc_l + 16);
        CPC();
    }

    for (int kc = 0; kc < 16; kc++) {
        int buf = kc & 1;
        {
            int koff = kc * 32 + aq * 8;
            const float4* wq4 = (const float4*)(g_wqs + koff);
            const float4* wk4 = (const float4*)(g_wks + koff);
            const float4* wv4 = (const float4*)(g_wvs + koff);
            float4 a0 = wq4[0], a1 = wq4[1];
            dq += xa.x*a0.x + xa.y*a0.y + xa.z*a0.z + xa.w*a0.w
                + xb.x*a1.x + xb.y*a1.y + xb.z*a1.z + xb.w*a1.w;
            float4 b0 = wk4[0], b1 = wk4[1];
            dk += xa.x*b0.x + xa.y*b0.y + xa.z*b0.z + xa.w*b0.w
                + xb.x*b1.x + xb.y*b1.y + xb.z*b1.z + xb.w*b1.w;
            float4 c0 = wv4[0], c1 = wv4[1];
            dv += xa.x*c0.x + xa.y*c0.y + xa.z*c0.z + xa.w*c0.w
                + xb.x*c1.x + xb.y*c1.y + xb.z*c1.z + xb.w*c1.w;
        }
        {
            __nv_bfloat16 h0 = __float2bfloat16_rn(xa.x), h1 = __float2bfloat16_rn(xa.y);
            __nv_bfloat16 h2 = __float2bfloat16_rn(xa.z), h3 = __float2bfloat16_rn(xa.w);
            __nv_bfloat16 h4 = __float2bfloat16_rn(xb.x), h5 = __float2bfloat16_rn(xb.y);
            __nv_bfloat16 h6 = __float2bfloat16_rn(xb.z), h7 = __float2bfloat16_rn(xb.w);
            uint4 hw, lw;
            hw.x = pk2(h0, h1); hw.y = pk2(h2, h3); hw.z = pk2(h4, h5); hw.w = pk2(h6, h7);
            lw.x = pkf(xa.x - __bfloat162float(h0), xa.y - __bfloat162float(h1));
            lw.y = pkf(xa.z - __bfloat162float(h2), xa.w - __bfloat162float(h3));
            lw.z = pkf(xb.x - __bfloat162float(h4), xb.y - __bfloat162float(h5));
            lw.w = pkf(xb.z - __bfloat162float(h6), xb.w - __bfloat162float(h7));
            uint32_t abase = PJ_A + buf * 8192;
            *(uint4*)(sm + tadr(abase, ar, aq*16))      = hw;
            *(uint4*)(sm + tadr(abase, ar, 64 + aq*16)) = lw;
        }
        if (kc < 15) {
            xa = *(const float4*)(arow_p + (kc + 1) * 32);
            xb = *(const float4*)(arow_p + (kc + 1) * 32 + 4);
        }
        if (kc < 15) {
            uint32_t bb = smb + PJ_B + (buf ^ 1) * 16384;
            const char* bh_p = bsrc_h + (kc + 1) * 64;
            const char* bl_p = bsrc_l + (kc + 1) * 64;
            CPA(tadr(bb, bn, bh*32),           bh_p);
            CPA(tadr(bb, bn, bh*32 + 16),      bh_p + 16);
            CPA(tadr(bb, bn, 64 + bh*32),      bl_p);
            CPA(tadr(bb, bn, 64 + bh*32 + 16), bl_p + 16);
            CPC();
            CPW1();
        } else {
            CPW0();
        }
        __syncthreads();

        uint32_t Ab = smb + PJ_A + buf * 8192;
        uint32_t Bb = smb + PJ_B + buf * 16384;
        #pragma unroll
        for (int ks = 0; ks < 2; ks++) {
            int akb = ks*32 + ((lane >> 4) << 4);
            int arw = m0 + (lane & 15);
            uint32_t ahi[2][4], alo[2][4];
            ldsm4(ahi[0], tadr(Ab, arw,      akb));
            ldsm4(ahi[1], tadr(Ab, arw + 16, akb));
            ldsm4(alo[0], tadr(Ab, arw,      akb + 64));
            ldsm4(alo[1], tadr(Ab, arw + 16, akb + 64));
            int brow = (lane & 7) | ((lane >> 4) << 3);
            int bkb = ks*32 + ((lane & 8) << 1);
            uint32_t bhi[4][2], blo[4][2];
            ldsm4(&bhi[0][0], tadr(Bb, n0 + brow,      bkb));
            ldsm4(&bhi[2][0], tadr(Bb, n0 + 16 + brow, bkb));
            ldsm4(&blo[0][0], tadr(Bb, n0 + brow,      bkb + 64));
            ldsm4(&blo[2][0], tadr(Bb, n0 + 16 + brow, bkb + 64));
            #pragma unroll
            for (int mf = 0; mf < 2; mf++)
                #pragma unroll
                for (int nf = 0; nf < 4; nf++) {
                    mma16816(C[mf][nf], ahi[mf], bhi[nf]);
                    mma16816(C[mf][nf], ahi[mf], blo[nf]);
                    mma16816(C[mf][nf], alo[mf], bhi[nf]);
                }
        }
    }

    // ---- finalize mask rowsums ----
    dq += __shfl_xor_sync(0xffffffffu, dq, 1);
    dq += __shfl_xor_sync(0xffffffffu, dq, 2);
    dk += __shfl_xor_sync(0xffffffffu, dk, 1);
    dk += __shfl_xor_sync(0xffffffffu, dk, 2);
    dv += __shfl_xor_sync(0xffffffffu, dv, 1);
    dv += __shfl_xor_sync(0xffffffffu, dv, 2);
    if (aq == 0) {
        float qs = dq + g_bs[0];
        float ks_ = dk + g_bs[1];
        float vs = dv + g_bs[2];
        g_wz[rowbase + ar] = make_float2((qs != 0.f) ? vs : 0.f,
                                         (ks_ == 0.f) ? 1.f : 0.f);
    }

    // ---- epilogue: bias, Q pre-scaled, fp16 store ----
    __half* dst; const float* bias; int nb; float scl;
    if (wn < 2) { dst = g_Qh; bias = bq; nb = wn * 32; scl = SC2F; }
    else        { dst = g_Kh; bias = bk; nb = (wn - 2) * 32; scl = 1.0f; }
    #pragma unroll
    for (int mf = 0; mf < 2; mf++) {
        int r0 = rowbase + m0 + mf*16 + (lane >> 2);
        #pragma unroll
        for (int nf = 0; nf < 4; nf++) {
            int c = nb + nf*8 + (lane & 3)*2;
            float b0 = __ldg(bias + c), b1 = __ldg(bias + c + 1);
            *(uint32_t*)(dst + (size_t)r0*AA + c) =
                pkh((C[mf][nf][0] + b0) * scl, (C[mf][nf][1] + b1) * scl);
            *(uint32_t*)(dst + (size_t)(r0+8)*AA + c) =
                pkh((C[mf][nf][2] + b0) * scl, (C[mf][nf][3] + b1) * scl);
        }
    }
}

// ---------------- kernel 2: fp16 flash attention (2.1M MMAs) ----------------
// grid (16 q-tiles, BB, 4 kv-splits); CTA 128 thr; 128q/CTA, 32q/warp; 8 key tiles of 64.
#define AT_Q   0                   // 16K (128 rows x 128B)
#define AT_K   16384               // 2 bufs x 8K
#define AT_WS  32768               // 2 x 512B
#define AT_SMEM (32768 + 1024)
#define NKT_SPLIT 8

__global__ __launch_bounds__(128, 4) void k_attn_mma() {
    extern __shared__ char sm[];
    uint32_t smb = smem_u32(sm);
    int tid = threadIdx.x;
    int lane = tid & 31;
    int wid = tid >> 5;
    int b = blockIdx.y;
    int z = blockIdx.z;
    int qrow0 = b * TT + blockIdx.x * 128;
    int kbase = b * TT + z * (NKT_SPLIT * 64);
    int wq0 = wid * 32;

    // load Q tile (swizzled): 128 rows x 128B
    {
        int r = tid;
        const uint4* src = (const uint4*)(g_Qh + (size_t)(qrow0 + r) * AA);
        #pragma unroll
        for (int j = 0; j < 8; j++)
            *(uint4*)(sm + tadr(AT_Q, r, j*16)) = src[j];
    }

    // prime K tile 0 + wz
    {
        int r = tid & 63, half = tid >> 6;
        const char* src = (const char*)(g_Kh + (size_t)(kbase + r) * AA) + half * 64;
        uint32_t base = smb + AT_K;
        #pragma unroll
        for (int j = 0; j < 4; j++) CPA(tadr(base, r, half*64 + j*16), src + j*16);
        if (tid < 32) CPA(smb + AT_WS + tid*16, (const char*)(g_wz + kbase) + tid*16);
        CPC();
    }
    CPW0();
    __syncthreads();

    // hoist Q fragments (loop-invariant): 32 regs
    uint32_t qf[4][2][4];
    #pragma unroll
    for (int ks = 0; ks < 4; ks++) {
        int akb = ks*32 + ((lane >> 4) << 4);
        #pragma unroll
        for (int mf = 0; mf < 2; mf++) {
            int arw = wq0 + mf*16 + (lane & 15);
            ldsm4(qf[ks][mf], tadr(smb + AT_Q, arw, akb));
        }
    }

    const float KZ2 = 1.4426950408889634e-8f;
    float l[4], acc[4];
    #pragma unroll
    for (int h = 0; h < 4; h++) { l[h] = 0.f; acc[h] = 0.f; }

    for (int kt = 0; kt < NKT_SPLIT; kt++) {
        int buf = kt & 1;
        if (kt + 1 < NKT_SPLIT) {
            int krow0 = kbase + (kt + 1) * 64;
            int r = tid & 63, half = tid >> 6;
            const char* src = (const char*)(g_Kh + (size_t)(krow0 + r) * AA) + half * 64;
            uint32_t base = smb + AT_K + (buf ^ 1) * 8192;
            #pragma unroll
            for (int j = 0; j < 4; j++) CPA(tadr(base, r, half*64 + j*16), src + j*16);
            if (tid < 32) CPA(smb + AT_WS + (buf ^ 1) * 512 + tid*16,
                              (const char*)(g_wz + krow0) + tid*16);
            CPC();
        }

        uint32_t kb = smb + AT_K + buf * 8192;
        const float2* wkp = (const float2*)(sm + AT_WS + buf * 512);
        int brow = (lane & 7) | ((lane >> 4) << 3);

        #pragma unroll
        for (int nfp = 0; nfp < 4; nfp++) {
            float C[2][2][4];
            #pragma unroll
            for (int mf = 0; mf < 2; mf++)
                #pragma unroll
                for (int nh = 0; nh < 2; nh++)
                    #pragma unroll
                    for (int c = 0; c < 4; c++) C[mf][nh][c] = 0.f;

            #pragma unroll
            for (int ks = 0; ks < 4; ks++) {
                int bkb = ks*32 + ((lane & 8) << 1);
                uint32_t bf[4];
                ldsm4(bf, tadr(kb, nfp*16 + brow, bkb));
                #pragma unroll
                for (int mf = 0; mf < 2; mf++) {
                    mma16816h(C[mf][0], qf[ks][mf], &bf[0]);
                    mma16816h(C[mf][1], qf[ks][mf], &bf[2]);
                }
            }

            #pragma unroll
            for (int nh = 0; nh < 2; nh++) {
                #pragma unroll
                for (int j2 = 0; j2 < 2; j2++) {
                    int col = nfp*16 + nh*8 + (lane & 3)*2 + j2;
                    float2 wk = wkp[col];
                    #pragma unroll
                    for (int mf = 0; mf < 2; mf++)
                        #pragma unroll
                        for (int h = 0; h < 2; h++) {
                            float raw = C[mf][nh][(h << 1) + j2];
                            float v = (wk.y != 0.f) ? KZ2 : raw;
                            float p = ex2f(v);
                            l[mf*2 + h] += p;
                            acc[mf*2 + h] += p * wk.x;
                        }
                }
            }
        }

        if (kt + 1 < NKT_SPLIT) CPW0();
        __syncthreads();
    }

    #pragma unroll
    for (int mf = 0; mf < 2; mf++)
        #pragma unroll
        for (int h = 0; h < 2; h++) {
            float lv = l[mf*2 + h], av = acc[mf*2 + h];
            lv += __shfl_xor_sync(0xffffffffu, lv, 1);
            lv += __shfl_xor_sync(0xffffffffu, lv, 2);
            av += __shfl_xor_sync(0xffffffffu, av, 1);
            av += __shfl_xor_sync(0xffffffffu, av, 2);
            if ((lane & 3) == 0) {
                int row = qrow0 + wq0 + mf*16 + h*8 + (lane >> 2);
                atomicAdd(&g_l[row], lv);
                atomicAdd(&g_acc[row], av);
            }
        }
}

// ---------------- kernel 3: out[b,d] += sum_t inp[b,t,d] * (acc[t]/l[t]) ----------------
__global__ __launch_bounds__(128) void k_out2(const float* __restrict__ inp,
                                              float* __restrict__ out) {
    __shared__ float c_sm[64];
    int b = blockIdx.y;
    int ts = blockIdx.x;
    int td = threadIdx.x;
    if (td < 64) {
        int idx = b * TT + ts * 64 + td;
        c_sm[td] = g_acc[idx] / g_l[idx];
    }
    __syncthreads();
    const float4* ip = (const float4*)(inp + (size_t)b * TT * DD) + (size_t)(ts * 64) * 128 + td;
    float4 acc = make_float4(0.f, 0.f, 0.f, 0.f);
    #pragma unroll 8
    for (int t = 0; t < 64; t++) {
        float4 x = ip[(size_t)t * 128];
        float cv = c_sm[t];
        acc.x += x.x * cv; acc.y += x.y * cv;
        acc.z += x.z * cv; acc.w += x.w * cv;
    }
    float* op = out + b * DD + td * 4;
    atomicAdd(op + 0, acc.x);
    atomicAdd(op + 1, acc.y);
    atomicAdd(op + 2, acc.z);
    atomicAdd(op + 3, acc.w);
}

// ---------------- launch ----------------
extern "C" void kernel_launch(void* const* d_in, const int* in_sizes, int n_in,
                              void* d_out, int out_size) {
    const float* inp = (const float*)d_in[0];
    const float* Wq  = (const float*)d_in[1];
    const float* bq  = (const float*)d_in[2];
    const float* Wk  = (const float*)d_in[3];
    const float* bk  = (const float*)d_in[4];
    const float* Wv  = (const float*)d_in[5];
    const float* bv  = (const float*)d_in[6];
    float* out = (float*)d_out;

    static int inited = 0;
    if (!inited) {
        cudaFuncSetAttribute(k_proj_mma, cudaFuncAttributeMaxDynamicSharedMemorySize, PJ_SMEM);
        cudaFuncSetAttribute(k_attn_mma, cudaFuncAttributeMaxDynamicSharedMemorySize, AT_SMEM);
        inited = 1;
    }

    k_zero<<<64, 512>>>(out);                                  // launch 1
    k_wsum<<<64, 256>>>(Wq, Wk, Wv, bq, bk, bv);               // launch 2
    k_proj_mma<<<NROWS / 64, 256, PJ_SMEM>>>(inp, bq, bk);     // launch 3
    k_attn_mma<<<dim3(TT / 128, BB, 4), 128, AT_SMEM>>>();     // launch 4 (profiled)
    k_out2<<<dim3(32, BB), 128>>>(inp, out);                   // launch 5
}

// round 16
// speedup vs baseline: 1.5025x; 1.1231x over previous
#include <cuda_runtime.h>
#include <cuda_bf16.h>
#include <cuda_fp16.h>
#include <cstdint>

#define BB 16
#define TT 2048
#define DD 512
#define AA 64
#define NROWS (BB*TT)

// ---------------- device scratch ----------------
__device__ __align__(16) __half g_Qh[NROWS*AA];   // fp16, pre-scaled by 0.125*log2e
__device__ __align__(16) __half g_Kh[NROWS*AA];   // fp16
__device__ __align__(16) __half g_WTh[128*DD];    // [n][k] fp16, n: 0..63 Q, 64..127 K
__device__ __align__(16) float2 g_wz[NROWS];
__device__ __align__(16) float g_l[NROWS];
__device__ __align__(16) float g_acc[NROWS];
__device__ float g_wqs[DD], g_wks[DD], g_wvs[DD];
__device__ float g_bs[3];

#define SC2F 0.18033688011112043f   // 0.125 * log2(e)

// ---------------- helpers ----------------
__device__ __forceinline__ uint32_t smem_u32(const void* p) {
    return (uint32_t)__cvta_generic_to_shared(p);
}
__device__ __forceinline__ float ex2f(float x) {
    float y; asm("ex2.approx.ftz.f32 %0, %1;" : "=f"(y) : "f"(x)); return y;
}
__device__ __forceinline__ void ldsm4(uint32_t* r, uint32_t addr) {
    asm volatile("ldmatrix.sync.aligned.m8n8.x4.shared.b16 {%0,%1,%2,%3}, [%4];"
        : "=r"(r[0]), "=r"(r[1]), "=r"(r[2]), "=r"(r[3]) : "r"(addr));
}
__device__ __forceinline__ void mma16816h(float* c, const uint32_t* a, const uint32_t* b) {
    asm volatile("mma.sync.aligned.m16n8k16.row.col.f32.f16.f16.f32 "
        "{%0,%1,%2,%3}, {%4,%5,%6,%7}, {%8,%9}, {%0,%1,%2,%3};"
        : "+f"(c[0]), "+f"(c[1]), "+f"(c[2]), "+f"(c[3])
        : "r"(a[0]), "r"(a[1]), "r"(a[2]), "r"(a[3]), "r"(b[0]), "r"(b[1]));
}
#define CPA(dst, src) asm volatile("cp.async.cg.shared.global [%0], [%1], 16;" :: "r"(dst), "l"(src))
#define CPC() asm volatile("cp.async.commit_group;" ::: "memory")
#define CPW0() asm volatile("cp.async.wait_group 0;" ::: "memory")
#define CPW1() asm volatile("cp.async.wait_group 1;" ::: "memory")

// 128-byte rows, xor swizzle (bits 4-6) for conflict-free ldmatrix
__device__ __forceinline__ uint32_t tadr(uint32_t base, int r, int kb) {
    return base + ((((uint32_t)r << 7) | (uint32_t)kb) ^ (((uint32_t)(r & 7)) << 4));
}
__device__ __forceinline__ uint32_t pkh(float a, float b) {
    __half2 t = __floats2half2_rn(a, b);
    return *reinterpret_cast<uint32_t*>(&t);
}

// ---------------- kernel A: zero out + l/acc partials ----------------
__global__ __launch_bounds__(512) void k_zero(float* __restrict__ out) {
    int idx = blockIdx.x * 512 + threadIdx.x;
    g_l[idx] = 0.f;
    g_acc[idx] = 0.f;
    if (blockIdx.x < 16) out[blockIdx.x * 512 + threadIdx.x] = 0.f;
}

// ---------------- kernel 0: W col sums + fp16 transpose ----------------
__global__ __launch_bounds__(256) void k_wsum(const float* __restrict__ Wq, const float* __restrict__ Wk,
                       const float* __restrict__ Wv,
                       const float* __restrict__ bq, const float* __restrict__ bk,
                       const float* __restrict__ bv) {
    int wid = threadIdx.x >> 5, lane = threadIdx.x & 31;
    int d = blockIdx.x * 8 + wid;

    float wq0 = Wq[d*AA + lane],      wq1 = Wq[d*AA + 32 + lane];
    float wk0 = Wk[d*AA + lane],      wk1 = Wk[d*AA + 32 + lane];
    float wv0 = Wv[d*AA + lane],      wv1 = Wv[d*AA + 32 + lane];

    float sq = wq0 + wq1, sk = wk0 + wk1, sv = wv0 + wv1;
    #pragma unroll
    for (int off = 16; off > 0; off >>= 1) {
        sq += __shfl_xor_sync(0xffffffffu, sq, off);
        sk += __shfl_xor_sync(0xffffffffu, sk, off);
        sv += __shfl_xor_sync(0xffffffffu, sv, off);
    }
    if (lane == 0) { g_wqs[d] = sq; g_wks[d] = sk; g_wvs[d] = sv; }

    #pragma unroll
    for (int half = 0; half < 2; half++) {
        int a = lane + half * 32;
        float vq = half ? wq1 : wq0;
        float vk = half ? wk1 : wk0;
        g_WTh[a*DD + d]        = __float2half_rn(vq);
        g_WTh[(64 + a)*DD + d] = __float2half_rn(vk);
    }

    if (blockIdx.x == 0 && threadIdx.x < 3) {
        const float* bb = (threadIdx.x == 0) ? bq : (threadIdx.x == 1) ? bk : bv;
        float s = 0.f;
        #pragma unroll 8
        for (int a = 0; a < AA; a++) s += bb[a];
        g_bs[threadIdx.x] = s;
    }
}

// ---------------- kernel 1: fp16 HMMA Q,K projection + fused mask rowsums ----------------
// CTA 256 thr (8 warps: 2m x 4n). Tile: 64 rows x 128 cols. K=512 in 8 chunks of 64.
// A: 64 rows x 64 k fp16 = 128B/row. B: 128 n x 64 k fp16 = 128B/row. 1.05M MMAs total.
#define PJ_A 0                    // 2 bufs x 8K
#define PJ_B 16384                // 2 bufs x 16K
#define PJ_SMEM (16384 + 32768)

__global__ __launch_bounds__(256) void k_proj_mma(const float* __restrict__ inp,
                                                  const float* __restrict__ bq,
                                                  const float* __restrict__ bk) {
    extern __shared__ char sm[];
    uint32_t smb = smem_u32(sm);
    int tid = threadIdx.x;
    int lane = tid & 31;
    int wid = tid >> 5;
    int m0 = (wid >> 2) * 32;
    int wn = wid & 3;
    int n0 = wn * 32;
    int rowbase = blockIdx.x * 64;

    int ar = tid >> 2, aq = tid & 3;   // A: row, 16-k quarter
    int bn = tid >> 1, bh = tid & 1;   // B: n row, 64B half

    float C[2][4][4];
    #pragma unroll
    for (int a = 0; a < 2; a++)
        #pragma unroll
        for (int b = 0; b < 4; b++)
            #pragma unroll
            for (int c = 0; c < 4; c++) C[a][b][c] = 0.f;
    float dq = 0.f, dk = 0.f, dv = 0.f;

    const float* arow_p = inp + (size_t)(rowbase + ar) * DD + aq * 16;
    const char* bsrc = (const char*)g_WTh + (size_t)bn * 1024 + bh * 64;

    // prime: A(0) regs + B(0) cp.async
    float4 x0 = *(const float4*)(arow_p);
    float4 x1 = *(const float4*)(arow_p + 4);
    float4 x2 = *(const float4*)(arow_p + 8);
    float4 x3 = *(const float4*)(arow_p + 12);
    {
        uint32_t bb = smb + PJ_B;
        #pragma unroll
        for (int j = 0; j < 4; j++) CPA(tadr(bb, bn, bh*64 + j*16), bsrc + j*16);
        CPC();
    }

    for (int kc = 0; kc < 8; kc++) {
        int buf = kc & 1;
        // mask dot products on current regs (fp32-exact)
        {
            int koff = kc * 64 + aq * 16;
            const float4* wq4 = (const float4*)(g_wqs + koff);
            const float4* wk4 = (const float4*)(g_wks + koff);
            const float4* wv4 = (const float4*)(g_wvs + koff);
            #pragma unroll
            for (int j = 0; j < 4; j++) {
                float4 x = (j == 0) ? x0 : (j == 1) ? x1 : (j == 2) ? x2 : x3;
                float4 a = wq4[j], bq_ = wk4[j], cv = wv4[j];
                dq += x.x*a.x + x.y*a.y + x.z*a.z + x.w*a.w;
                dk += x.x*bq_.x + x.y*bq_.y + x.z*bq_.z + x.w*bq_.w;
                dv += x.x*cv.x + x.y*cv.y + x.z*cv.z + x.w*cv.w;
            }
        }
        // convert fp32 -> fp16, STS (16 halves = 32 B)
        {
            uint4 h0, h1;
            h0.x = pkh(x0.x, x0.y); h0.y = pkh(x0.z, x0.w);
            h0.z = pkh(x1.x, x1.y); h0.w = pkh(x1.z, x1.w);
            h1.x = pkh(x2.x, x2.y); h1.y = pkh(x2.z, x2.w);
            h1.z = pkh(x3.x, x3.y); h1.w = pkh(x3.z, x3.w);
            uint32_t abase = PJ_A + buf * 8192;
            *(uint4*)(sm + tadr(abase, ar, aq*32))      = h0;
            *(uint4*)(sm + tadr(abase, ar, aq*32 + 16)) = h1;
        }
        // LDG A(kc+1) early
        if (kc < 7) {
            x0 = *(const float4*)(arow_p + (kc + 1) * 64);
            x1 = *(const float4*)(arow_p + (kc + 1) * 64 + 4);
            x2 = *(const float4*)(arow_p + (kc + 1) * 64 + 8);
            x3 = *(const float4*)(arow_p + (kc + 1) * 64 + 12);
        }
        // prefetch B(kc+1)
        if (kc < 7) {
            uint32_t bb = smb + PJ_B + (buf ^ 1) * 16384;
            const char* bp = bsrc + (kc + 1) * 128;
            #pragma unroll
            for (int j = 0; j < 4; j++) CPA(tadr(bb, bn, bh*64 + j*16), bp + j*16);
            CPC();
            CPW1();
        } else {
            CPW0();
        }
        __syncthreads();

        uint32_t Ab = smb + PJ_A + buf * 8192;
        uint32_t Bb = smb + PJ_B + buf * 16384;
        #pragma unroll
        for (int ks = 0; ks < 4; ks++) {
            int akb = ks*32 + ((lane >> 4) << 4);
            int arw = m0 + (lane & 15);
            uint32_t af[2][4];
            ldsm4(af[0], tadr(Ab, arw,      akb));
            ldsm4(af[1], tadr(Ab, arw + 16, akb));
            int brow = (lane & 7) | ((lane >> 4) << 3);
            int bkb = ks*32 + ((lane & 8) << 1);
            uint32_t bf[4][2];
            ldsm4(&bf[0][0], tadr(Bb, n0 + brow,      bkb));
            ldsm4(&bf[2][0], tadr(Bb, n0 + 16 + brow, bkb));
            #pragma unroll
            for (int mf = 0; mf < 2; mf++)
                #pragma unroll
                for (int nf = 0; nf < 4; nf++)
                    mma16816h(C[mf][nf], af[mf], bf[nf]);
        }
    }

    // ---- finalize mask rowsums (4 lanes per row) ----
    dq += __shfl_xor_sync(0xffffffffu, dq, 1);
    dq += __shfl_xor_sync(0xffffffffu, dq, 2);
    dk += __shfl_xor_sync(0xffffffffu, dk, 1);
    dk += __shfl_xor_sync(0xffffffffu, dk, 2);
    dv += __shfl_xor_sync(0xffffffffu, dv, 1);
    dv += __shfl_xor_sync(0xffffffffu, dv, 2);
    if (aq == 0) {
        float qs = dq + g_bs[0];
        float ks_ = dk + g_bs[1];
        float vs = dv + g_bs[2];
        g_wz[rowbase + ar] = make_float2((qs != 0.f) ? vs : 0.f,
                                         (ks_ == 0.f) ? 1.f : 0.f);
    }

    // ---- epilogue: bias, Q pre-scaled, fp16 store ----
    __half* dst; const float* bias; int nb; float scl;
    if (wn < 2) { dst = g_Qh; bias = bq; nb = wn * 32; scl = SC2F; }
    else        { dst = g_Kh; bias = bk; nb = (wn - 2) * 32; scl = 1.0f; }
    #pragma unroll
    for (int mf = 0; mf < 2; mf++) {
        int r0 = rowbase + m0 + mf*16 + (lane >> 2);
        #pragma unroll
        for (int nf = 0; nf < 4; nf++) {
            int c = nb + nf*8 + (lane & 3)*2;
            float b0 = __ldg(bias + c), b1 = __ldg(bias + c + 1);
            *(uint32_t*)(dst + (size_t)r0*AA + c) =
                pkh((C[mf][nf][0] + b0) * scl, (C[mf][nf][1] + b1) * scl);
            *(uint32_t*)(dst + (size_t)(r0+8)*AA + c) =
                pkh((C[mf][nf][2] + b0) * scl, (C[mf][nf][3] + b1) * scl);
        }
    }
}

// ---------------- kernel 2: fp16 flash attention (2.1M MMAs) ----------------
#define AT_Q   0                   // 16K (128 rows x 128B)
#define AT_K   16384               // 2 bufs x 8K
#define AT_WS  32768               // 2 x 512B
#define AT_SMEM (32768 + 1024)
#define NKT_SPLIT 8

__global__ __launch_bounds__(128, 4) void k_attn_mma() {
    extern __shared__ char sm[];
    uint32_t smb = smem_u32(sm);
    int tid = threadIdx.x;
    int lane = tid & 31;
    int wid = tid >> 5;
    int b = blockIdx.y;
    int z = blockIdx.z;
    int qrow0 = b * TT + blockIdx.x * 128;
    int kbase = b * TT + z * (NKT_SPLIT * 64);
    int wq0 = wid * 32;

    // load Q tile (swizzled)
    {
        int r = tid;
        const uint4* src = (const uint4*)(g_Qh + (size_t)(qrow0 + r) * AA);
        #pragma unroll
        for (int j = 0; j < 8; j++)
            *(uint4*)(sm + tadr(AT_Q, r, j*16)) = src[j];
    }

    // prime K tile 0 + wz
    {
        int r = tid & 63, half = tid >> 6;
        const char* src = (const char*)(g_Kh + (size_t)(kbase + r) * AA) + half * 64;
        uint32_t base = smb + AT_K;
        #pragma unroll
        for (int j = 0; j < 4; j++) CPA(tadr(base, r, half*64 + j*16), src + j*16);
        if (tid < 32) CPA(smb + AT_WS + tid*16, (const char*)(g_wz + kbase) + tid*16);
        CPC();
    }
    CPW0();
    __syncthreads();

    // hoist Q fragments (loop-invariant)
    uint32_t qf[4][2][4];
    #pragma unroll
    for (int ks = 0; ks < 4; ks++) {
        int akb = ks*32 + ((lane >> 4) << 4);
        #pragma unroll
        for (int mf = 0; mf < 2; mf++) {
            int arw = wq0 + mf*16 + (lane & 15);
            ldsm4(qf[ks][mf], tadr(smb + AT_Q, arw, akb));
        }
    }

    const float KZ2 = 1.4426950408889634e-8f;
    float l[4], acc[4];
    #pragma unroll
    for (int h = 0; h < 4; h++) { l[h] = 0.f; acc[h] = 0.f; }

    for (int kt = 0; kt < NKT_SPLIT; kt++) {
        int buf = kt & 1;
        if (kt + 1 < NKT_SPLIT) {
            int krow0 = kbase + (kt + 1) * 64;
            int r = tid & 63, half = tid >> 6;
            const char* src = (const char*)(g_Kh + (size_t)(krow0 + r) * AA) + half * 64;
            uint32_t base = smb + AT_K + (buf ^ 1) * 8192;
            #pragma unroll
            for (int j = 0; j < 4; j++) CPA(tadr(base, r, half*64 + j*16), src + j*16);
            if (tid < 32) CPA(smb + AT_WS + (buf ^ 1) * 512 + tid*16,
                              (const char*)(g_wz + krow0) + tid*16);
            CPC();
        }

        uint32_t kb = smb + AT_K + buf * 8192;
        const float2* wkp = (const float2*)(sm + AT_WS + buf * 512);
        int brow = (lane & 7) | ((lane >> 4) << 3);

        #pragma unroll
        for (int nfp = 0; nfp < 4; nfp++) {
            float C[2][2][4];
            #pragma unroll
            for (int mf = 0; mf < 2; mf++)
                #pragma unroll
                for (int nh = 0; nh < 2; nh++)
                    #pragma unroll
                    for (int c = 0; c < 4; c++) C[mf][nh][c] = 0.f;

            #pragma unroll
            for (int ks = 0; ks < 4; ks++) {
                int bkb = ks*32 + ((lane & 8) << 1);
                uint32_t bf[4];
                ldsm4(bf, tadr(kb, nfp*16 + brow, bkb));
                #pragma unroll
                for (int mf = 0; mf < 2; mf++) {
                    mma16816h(C[mf][0], qf[ks][mf], &bf[0]);
                    mma16816h(C[mf][1], qf[ks][mf], &bf[2]);
                }
            }

            #pragma unroll
            for (int nh = 0; nh < 2; nh++) {
                #pragma unroll
                for (int j2 = 0; j2 < 2; j2++) {
                    int col = nfp*16 + nh*8 + (lane & 3)*2 + j2;
                    float2 wk = wkp[col];
                    #pragma unroll
                    for (int mf = 0; mf < 2; mf++)
                        #pragma unroll
                        for (int h = 0; h < 2; h++) {
                            float raw = C[mf][nh][(h << 1) + j2];
                            float v = (wk.y != 0.f) ? KZ2 : raw;
                            float p = ex2f(v);
                            l[mf*2 + h] += p;
                            acc[mf*2 + h] += p * wk.x;
                        }
                }
            }
        }

        if (kt + 1 < NKT_SPLIT) CPW0();
        __syncthreads();
    }

    #pragma unroll
    for (int mf = 0; mf < 2; mf++)
        #pragma unroll
        for (int h = 0; h < 2; h++) {
            float lv = l[mf*2 + h], av = acc[mf*2 + h];
            lv += __shfl_xor_sync(0xffffffffu, lv, 1);
            lv += __shfl_xor_sync(0xffffffffu, lv, 2);
            av += __shfl_xor_sync(0xffffffffu, av, 1);
            av += __shfl_xor_sync(0xffffffffu, av, 2);
            if ((lane & 3) == 0) {
                int row = qrow0 + wq0 + mf*16 + h*8 + (lane >> 2);
                atomicAdd(&g_l[row], lv);
                atomicAdd(&g_acc[row], av);
            }
        }
}

// ---------------- kernel 3: out[b,d] += sum_t inp[b,t,d] * (acc[t]/l[t]) ----------------
__global__ __launch_bounds__(128) void k_out2(const float* __restrict__ inp,
                                              float* __restrict__ out) {
    __shared__ float c_sm[64];
    int b = blockIdx.y;
    int ts = blockIdx.x;
    int td = threadIdx.x;
    if (td < 64) {
        int idx = b * TT + ts * 64 + td;
        c_sm[td] = g_acc[idx] / g_l[idx];
    }
    __syncthreads();
    const float4* ip = (const float4*)(inp + (size_t)b * TT * DD) + (size_t)(ts * 64) * 128 + td;
    float4 acc = make_float4(0.f, 0.f, 0.f, 0.f);
    #pragma unroll 8
    for (int t = 0; t < 64; t++) {
        float4 x = ip[(size_t)t * 128];
        float cv = c_sm[t];
        acc.x += x.x * cv; acc.y += x.y * cv;
        acc.z += x.z * cv; acc.w += x.w * cv;
    }
    float* op = out + b * DD + td * 4;
    atomicAdd(op + 0, acc.x);
    atomicAdd(op + 1, acc.y);
    atomicAdd(op + 2, acc.z);
    atomicAdd(op + 3, acc.w);
}

// ---------------- launch ----------------
extern "C" void kernel_launch(void* const* d_in, const int* in_sizes, int n_in,
                              void* d_out, int out_size) {
    const float* inp = (const float*)d_in[0];
    const float* Wq  = (const float*)d_in[1];
    const float* bq  = (const float*)d_in[2];
    const float* Wk  = (const float*)d_in[3];
    const float* bk  = (const float*)d_in[4];
    const float* Wv  = (const float*)d_in[5];
    const float* bv  = (const float*)d_in[6];
    float* out = (float*)d_out;

    static int inited = 0;
    if (!inited) {
        cudaFuncSetAttribute(k_proj_mma, cudaFuncAttributeMaxDynamicSharedMemorySize, PJ_SMEM);
        cudaFuncSetAttribute(k_attn_mma, cudaFuncAttributeMaxDynamicSharedMemorySize, AT_SMEM);
        inited = 1;
    }

    k_zero<<<64, 512>>>(out);                                  // launch 1
    k_wsum<<<64, 256>>>(Wq, Wk, Wv, bq, bk, bv);               // launch 2
    k_proj_mma<<<NROWS / 64, 256, PJ_SMEM>>>(inp, bq, bk);     // launch 3
    k_attn_mma<<<dim3(TT / 128, BB, 4), 128, AT_SMEM>>>();     // launch 4 (profiled)
    k_out2<<<dim3(32, BB), 128>>>(inp, out);                   // launch 5
}

// round 17
// speedup vs baseline: 1.5050x; 1.0017x over previous
#include <cuda_runtime.h>
#include <cuda_fp16.h>
#include <cstdint>

#define BB 16
#define TT 2048
#define DD 512
#define AA 64
#define NROWS (BB*TT)

// ---------------- device scratch ----------------
__device__ __align__(16) __half g_Qh[NROWS*AA];   // fp16, pre-scaled by 0.125*log2e
__device__ __align__(16) __half g_Kh[NROWS*AA];   // fp16, masked rows zeroed
__device__ __align__(16) __half g_WTh[128*DD];    // [n][k] fp16
__device__ __align__(16) float g_w[NROWS];        // q_mask * vsum per key row
__device__ __align__(16) float g_l4[4*NROWS];     // per-kv-split softmax denominators
__device__ __align__(16) float g_acc4[4*NROWS];   // per-kv-split numerators
__device__ float g_wqs[DD], g_wks[DD], g_wvs[DD];
__device__ float g_bs[3];

#define SC2F 0.18033688011112043f   // 0.125 * log2(e)

// ---------------- helpers ----------------
__device__ __forceinline__ uint32_t smem_u32(const void* p) {
    return (uint32_t)__cvta_generic_to_shared(p);
}
__device__ __forceinline__ float ex2f(float x) {
    float y; asm("ex2.approx.ftz.f32 %0, %1;" : "=f"(y) : "f"(x)); return y;
}
__device__ __forceinline__ void ldsm4(uint32_t* r, uint32_t addr) {
    asm volatile("ldmatrix.sync.aligned.m8n8.x4.shared.b16 {%0,%1,%2,%3}, [%4];"
        : "=r"(r[0]), "=r"(r[1]), "=r"(r[2]), "=r"(r[3]) : "r"(addr));
}
__device__ __forceinline__ void mma16816h(float* c, const uint32_t* a, const uint32_t* b) {
    asm volatile("mma.sync.aligned.m16n8k16.row.col.f32.f16.f16.f32 "
        "{%0,%1,%2,%3}, {%4,%5,%6,%7}, {%8,%9}, {%0,%1,%2,%3};"
        : "+f"(c[0]), "+f"(c[1]), "+f"(c[2]), "+f"(c[3])
        : "r"(a[0]), "r"(a[1]), "r"(a[2]), "r"(a[3]), "r"(b[0]), "r"(b[1]));
}
#define CPA(dst, src) asm volatile("cp.async.cg.shared.global [%0], [%1], 16;" :: "r"(dst), "l"(src))
#define CPC() asm volatile("cp.async.commit_group;" ::: "memory")
#define CPW0() asm volatile("cp.async.wait_group 0;" ::: "memory")
#define CPW1() asm volatile("cp.async.wait_group 1;" ::: "memory")

// 128-byte rows, xor swizzle (bits 4-6) for conflict-free ldmatrix
__device__ __forceinline__ uint32_t tadr(uint32_t base, int r, int kb) {
    return base + ((((uint32_t)r << 7) | (uint32_t)kb) ^ (((uint32_t)(r & 7)) << 4));
}
__device__ __forceinline__ uint32_t pkh(float a, float b) {
    __half2 t = __floats2half2_rn(a, b);
    return *reinterpret_cast<uint32_t*>(&t);
}

// ---------------- kernel A: zero output ----------------
__global__ __launch_bounds__(512) void k_zero(float* __restrict__ out) {
    out[blockIdx.x * 512 + threadIdx.x] = 0.f;
}

// ---------------- kernel 0: W col sums + fp16 transpose ----------------
__global__ __launch_bounds__(256) void k_wsum(const float* __restrict__ Wq, const float* __restrict__ Wk,
                       const float* __restrict__ Wv,
                       const float* __restrict__ bq, const float* __restrict__ bk,
                       const float* __restrict__ bv) {
    int wid = threadIdx.x >> 5, lane = threadIdx.x & 31;
    int d = blockIdx.x * 8 + wid;

    float wq0 = Wq[d*AA + lane],      wq1 = Wq[d*AA + 32 + lane];
    float wk0 = Wk[d*AA + lane],      wk1 = Wk[d*AA + 32 + lane];
    float wv0 = Wv[d*AA + lane],      wv1 = Wv[d*AA + 32 + lane];

    float sq = wq0 + wq1, sk = wk0 + wk1, sv = wv0 + wv1;
    #pragma unroll
    for (int off = 16; off > 0; off >>= 1) {
        sq += __shfl_xor_sync(0xffffffffu, sq, off);
        sk += __shfl_xor_sync(0xffffffffu, sk, off);
        sv += __shfl_xor_sync(0xffffffffu, sv, off);
    }
    if (lane == 0) { g_wqs[d] = sq; g_wks[d] = sk; g_wvs[d] = sv; }

    #pragma unroll
    for (int half = 0; half < 2; half++) {
        int a = lane + half * 32;
        float vq = half ? wq1 : wq0;
        float vk = half ? wk1 : wk0;
        g_WTh[a*DD + d]        = __float2half_rn(vq);
        g_WTh[(64 + a)*DD + d] = __float2half_rn(vk);
    }

    if (blockIdx.x == 0 && threadIdx.x < 3) {
        const float* bb = (threadIdx.x == 0) ? bq : (threadIdx.x == 1) ? bk : bv;
        float s = 0.f;
        #pragma unroll 8
        for (int a = 0; a < AA; a++) s += bb[a];
        g_bs[threadIdx.x] = s;
    }
}

// ---------------- kernel 1: fp16 HMMA Q,K projection + fused mask rowsums ----------------
#define PJ_A 0                    // 2 bufs x 8K
#define PJ_B 16384                // 2 bufs x 16K
#define PJ_SMEM (16384 + 32768)

__global__ __launch_bounds__(256) void k_proj_mma(const float* __restrict__ inp,
                                                  const float* __restrict__ bq,
                                                  const float* __restrict__ bk) {
    extern __shared__ char sm[];
    uint32_t smb = smem_u32(sm);
    int tid = threadIdx.x;
    int lane = tid & 31;
    int wid = tid >> 5;
    int m0 = (wid >> 2) * 32;
    int wn = wid & 3;
    int n0 = wn * 32;
    int rowbase = blockIdx.x * 64;

    int ar = tid >> 2, aq = tid & 3;   // A: row, 16-k quarter
    int bn = tid >> 1, bh = tid & 1;   // B: n row, 64B half

    float C[2][4][4];
    #pragma unroll
    for (int a = 0; a < 2; a++)
        #pragma unroll
        for (int b = 0; b < 4; b++)
            #pragma unroll
            for (int c = 0; c < 4; c++) C[a][b][c] = 0.f;
    float dq = 0.f, dk = 0.f, dv = 0.f;

    const float* arow_p = inp + (size_t)(rowbase + ar) * DD + aq * 16;
    const char* bsrc = (const char*)g_WTh + (size_t)bn * 1024 + bh * 64;

    float4 x0 = *(const float4*)(arow_p);
    float4 x1 = *(const float4*)(arow_p + 4);
    float4 x2 = *(const float4*)(arow_p + 8);
    float4 x3 = *(const float4*)(arow_p + 12);
    {
        uint32_t bb = smb + PJ_B;
        #pragma unroll
        for (int j = 0; j < 4; j++) CPA(tadr(bb, bn, bh*64 + j*16), bsrc + j*16);
        CPC();
    }

    for (int kc = 0; kc < 8; kc++) {
        int buf = kc & 1;
        {
            int koff = kc * 64 + aq * 16;
            const float4* wq4 = (const float4*)(g_wqs + koff);
            const float4* wk4 = (const float4*)(g_wks + koff);
            const float4* wv4 = (const float4*)(g_wvs + koff);
            #pragma unroll
            for (int j = 0; j < 4; j++) {
                float4 x = (j == 0) ? x0 : (j == 1) ? x1 : (j == 2) ? x2 : x3;
                float4 a = wq4[j], bq_ = wk4[j], cv = wv4[j];
                dq += x.x*a.x + x.y*a.y + x.z*a.z + x.w*a.w;
                dk += x.x*bq_.x + x.y*bq_.y + x.z*bq_.z + x.w*bq_.w;
                dv += x.x*cv.x + x.y*cv.y + x.z*cv.z + x.w*cv.w;
            }
        }
        {
            uint4 h0, h1;
            h0.x = pkh(x0.x, x0.y); h0.y = pkh(x0.z, x0.w);
            h0.z = pkh(x1.x, x1.y); h0.w = pkh(x1.z, x1.w);
            h1.x = pkh(x2.x, x2.y); h1.y = pkh(x2.z, x2.w);
            h1.z = pkh(x3.x, x3.y); h1.w = pkh(x3.z, x3.w);
            uint32_t abase = PJ_A + buf * 8192;
            *(uint4*)(sm + tadr(abase, ar, aq*32))      = h0;
            *(uint4*)(sm + tadr(abase, ar, aq*32 + 16)) = h1;
        }
        if (kc < 7) {
            x0 = *(const float4*)(arow_p + (kc + 1) * 64);
            x1 = *(const float4*)(arow_p + (kc + 1) * 64 + 4);
            x2 = *(const float4*)(arow_p + (kc + 1) * 64 + 8);
            x3 = *(const float4*)(arow_p + (kc + 1) * 64 + 12);
        }
        if (kc < 7) {
            uint32_t bb = smb + PJ_B + (buf ^ 1) * 16384;
            const char* bp = bsrc + (kc + 1) * 128;
            #pragma unroll
            for (int j = 0; j < 4; j++) CPA(tadr(bb, bn, bh*64 + j*16), bp + j*16);
            CPC();
            CPW1();
        } else {
            CPW0();
        }
        __syncthreads();

        uint32_t Ab = smb + PJ_A + buf * 8192;
        uint32_t Bb = smb + PJ_B + buf * 16384;
        #pragma unroll
        for (int ks = 0; ks < 4; ks++) {
            int akb = ks*32 + ((lane >> 4) << 4);
            int arw = m0 + (lane & 15);
            uint32_t af[2][4];
            ldsm4(af[0], tadr(Ab, arw,      akb));
            ldsm4(af[1], tadr(Ab, arw + 16, akb));
            int brow = (lane & 7) | ((lane >> 4) << 3);
            int bkb = ks*32 + ((lane & 8) << 1);
            uint32_t bf[4][2];
            ldsm4(&bf[0][0], tadr(Bb, n0 + brow,      bkb));
            ldsm4(&bf[2][0], tadr(Bb, n0 + 16 + brow, bkb));
            #pragma unroll
            for (int mf = 0; mf < 2; mf++)
                #pragma unroll
                for (int nf = 0; nf < 4; nf++)
                    mma16816h(C[mf][nf], af[mf], bf[nf]);
        }
    }

    // ---- finalize mask rowsums; broadcast kz scale via smem ----
    dq += __shfl_xor_sync(0xffffffffu, dq, 1);
    dq += __shfl_xor_sync(0xffffffffu, dq, 2);
    dk += __shfl_xor_sync(0xffffffffu, dk, 1);
    dk += __shfl_xor_sync(0xffffffffu, dk, 2);
    dv += __shfl_xor_sync(0xffffffffu, dv, 1);
    dv += __shfl_xor_sync(0xffffffffu, dv, 2);
    float* kzS = (float*)sm;   // buf-0 A region is free now
    if (aq == 0) {
        float qs = dq + g_bs[0];
        float ks_ = dk + g_bs[1];
        float vs = dv + g_bs[2];
        g_w[rowbase + ar] = (qs != 0.f) ? vs : 0.f;
        kzS[ar] = (ks_ == 0.f) ? 0.f : 1.f;   // 0 => zero the K row (score->0, exp->1)
    }
    __syncthreads();

    // ---- epilogue: bias, Q pre-scaled, K row-masked, fp16 store ----
    __half* dst; const float* bias; int nb; bool isQ = (wn < 2);
    if (isQ) { dst = g_Qh; bias = bq; nb = wn * 32; }
    else     { dst = g_Kh; bias = bk; nb = (wn - 2) * 32; }
    #pragma unroll
    for (int mf = 0; mf < 2; mf++) {
        int rr = m0 + mf*16 + (lane >> 2);
        int r0 = rowbase + rr;
        float s0 = isQ ? SC2F : kzS[rr];
        float s1 = isQ ? SC2F : kzS[rr + 8];
        #pragma unroll
        for (int nf = 0; nf < 4; nf++) {
            int c = nb + nf*8 + (lane & 3)*2;
            float b0 = __ldg(bias + c), b1 = __ldg(bias + c + 1);
            *(uint32_t*)(dst + (size_t)r0*AA + c) =
                pkh((C[mf][nf][0] + b0) * s0, (C[mf][nf][1] + b1) * s0);
            *(uint32_t*)(dst + (size_t)(r0+8)*AA + c) =
                pkh((C[mf][nf][2] + b0) * s1, (C[mf][nf][3] + b1) * s1);
        }
    }
}

// ---------------- kernel 2: fp16 flash attention, 3-op softmax, no atomics ----------------
#define AT_Q   0                   // 16K
#define AT_K   16384               // 2 bufs x 8K
#define AT_WS  32768               // 2 x 256B (float w per key)
#define AT_SMEM (32768 + 512)
#define NKT_SPLIT 8

__global__ __launch_bounds__(128, 4) void k_attn_mma() {
    extern __shared__ char sm[];
    uint32_t smb = smem_u32(sm);
    int tid = threadIdx.x;
    int lane = tid & 31;
    int wid = tid >> 5;
    int b = blockIdx.y;
    int z = blockIdx.z;
    int qrow0 = b * TT + blockIdx.x * 128;
    int kbase = b * TT + z * (NKT_SPLIT * 64);
    int wq0 = wid * 32;

    // load Q tile (swizzled)
    {
        int r = tid;
        const uint4* src = (const uint4*)(g_Qh + (size_t)(qrow0 + r) * AA);
        #pragma unroll
        for (int j = 0; j < 8; j++)
            *(uint4*)(sm + tadr(AT_Q, r, j*16)) = src[j];
    }

    // prime K tile 0 + w
    {
        int r = tid & 63, half = tid >> 6;
        const char* src = (const char*)(g_Kh + (size_t)(kbase + r) * AA) + half * 64;
        uint32_t base = smb + AT_K;
        #pragma unroll
        for (int j = 0; j < 4; j++) CPA(tadr(base, r, half*64 + j*16), src + j*16);
        if (tid < 16) CPA(smb + AT_WS + tid*16, (const char*)(g_w + kbase) + tid*16);
        CPC();
    }
    CPW0();
    __syncthreads();

    // hoist Q fragments
    uint32_t qf[4][2][4];
    #pragma unroll
    for (int ks = 0; ks < 4; ks++) {
        int akb = ks*32 + ((lane >> 4) << 4);
        #pragma unroll
        for (int mf = 0; mf < 2; mf++) {
            int arw = wq0 + mf*16 + (lane & 15);
            ldsm4(qf[ks][mf], tadr(smb + AT_Q, arw, akb));
        }
    }

    float l[4], acc[4];
    #pragma unroll
    for (int h = 0; h < 4; h++) { l[h] = 0.f; acc[h] = 0.f; }

    for (int kt = 0; kt < NKT_SPLIT; kt++) {
        int buf = kt & 1;
        if (kt + 1 < NKT_SPLIT) {
            int krow0 = kbase + (kt + 1) * 64;
            int r = tid & 63, half = tid >> 6;
            const char* src = (const char*)(g_Kh + (size_t)(krow0 + r) * AA) + half * 64;
            uint32_t base = smb + AT_K + (buf ^ 1) * 8192;
            #pragma unroll
            for (int j = 0; j < 4; j++) CPA(tadr(base, r, half*64 + j*16), src + j*16);
            if (tid < 16) CPA(smb + AT_WS + (buf ^ 1) * 256 + tid*16,
                              (const char*)(g_w + krow0) + tid*16);
            CPC();
        }

        uint32_t kb = smb + AT_K + buf * 8192;
        const float2* wkp = (const float2*)(sm + AT_WS + buf * 256);
        int brow = (lane & 7) | ((lane >> 4) << 3);

        #pragma unroll
        for (int nfp = 0; nfp < 4; nfp++) {
            float C[2][2][4];
            #pragma unroll
            for (int mf = 0; mf < 2; mf++)
                #pragma unroll
                for (int nh = 0; nh < 2; nh++)
                    #pragma unroll
                    for (int c = 0; c < 4; c++) C[mf][nh][c] = 0.f;

            #pragma unroll
            for (int ks = 0; ks < 4; ks++) {
                int bkb = ks*32 + ((lane & 8) << 1);
                uint32_t bf[4];
                ldsm4(bf, tadr(kb, nfp*16 + brow, bkb));
                #pragma unroll
                for (int mf = 0; mf < 2; mf++) {
                    mma16816h(C[mf][0], qf[ks][mf], &bf[0]);
                    mma16816h(C[mf][1], qf[ks][mf], &bf[2]);
                }
            }

            // 3-op softmax: p = ex2(raw); l += p; acc += p*w
            #pragma unroll
            for (int nh = 0; nh < 2; nh++) {
                float2 wv = wkp[(nfp*16 + nh*8) / 2 + (lane & 3)];
                #pragma unroll
                for (int mf = 0; mf < 2; mf++)
                    #pragma unroll
                    for (int h = 0; h < 2; h++) {
                        float p0 = ex2f(C[mf][nh][(h << 1)]);
                        float p1 = ex2f(C[mf][nh][(h << 1) + 1]);
                        l[mf*2 + h] += p0;
                        acc[mf*2 + h] += p0 * wv.x;
                        l[mf*2 + h] += p1;
                        acc[mf*2 + h] += p1 * wv.y;
                    }
            }
        }

        if (kt + 1 < NKT_SPLIT) CPW0();
        __syncthreads();
    }

    #pragma unroll
    for (int mf = 0; mf < 2; mf++)
        #pragma unroll
        for (int h = 0; h < 2; h++) {
            float lv = l[mf*2 + h], av = acc[mf*2 + h];
            lv += __shfl_xor_sync(0xffffffffu, lv, 1);
            lv += __shfl_xor_sync(0xffffffffu, lv, 2);
            av += __shfl_xor_sync(0xffffffffu, av, 1);
            av += __shfl_xor_sync(0xffffffffu, av, 2);
            if ((lane & 3) == 0) {
                int row = qrow0 + wq0 + mf*16 + h*8 + (lane >> 2);
                g_l4[(size_t)z * NROWS + row] = lv;      // unique owner: no atomic
                g_acc4[(size_t)z * NROWS + row] = av;
            }
        }
}

// ---------------- kernel 3: out[b,d] += sum_t inp[b,t,d] * (Σacc/Σl) ----------------
// grid (64 t-splits, BB), 128 threads; 32 t-rows per block
__global__ __launch_bounds__(128) void k_out2(const float* __restrict__ inp,
                                              float* __restrict__ out) {
    __shared__ float c_sm[32];
    int b = blockIdx.y;
    int ts = blockIdx.x;
    int td = threadIdx.x;
    if (td < 32) {
        int idx = b * TT + ts * 32 + td;
        float L = g_l4[idx] + g_l4[NROWS + idx] + g_l4[2*NROWS + idx] + g_l4[3*NROWS + idx];
        float A = g_acc4[idx] + g_acc4[NROWS + idx] + g_acc4[2*NROWS + idx] + g_acc4[3*NROWS + idx];
        c_sm[td] = A / L;
    }
    __syncthreads();
    const float4* ip = (const float4*)(inp + (size_t)b * TT * DD) + (size_t)(ts * 32) * 128 + td;
    float4 acc = make_float4(0.f, 0.f, 0.f, 0.f);
    #pragma unroll 8
    for (int t = 0; t < 32; t++) {
        float4 x = ip[(size_t)t * 128];
        float cv = c_sm[t];
        acc.x += x.x * cv; acc.y += x.y * cv;
        acc.z += x.z * cv; acc.w += x.w * cv;
    }
    float* op = out + b * DD + td * 4;
    atomicAdd(op + 0, acc.x);
    atomicAdd(op + 1, acc.y);
    atomicAdd(op + 2, acc.z);
    atomicAdd(op + 3, acc.w);
}

// ---------------- launch ----------------
extern "C" void kernel_launch(void* const* d_in, const int* in_sizes, int n_in,
                              void* d_out, int out_size) {
    const float* inp = (const float*)d_in[0];
    const float* Wq  = (const float*)d_in[1];
    const float* bq  = (const float*)d_in[2];
    const float* Wk  = (const float*)d_in[3];
    const float* bk  = (const float*)d_in[4];
    const float* Wv  = (const float*)d_in[5];
    const float* bv  = (const float*)d_in[6];
    float* out = (float*)d_out;

    static int inited = 0;
    if (!inited) {
        cudaFuncSetAttribute(k_proj_mma, cudaFuncAttributeMaxDynamicSharedMemorySize, PJ_SMEM);
        cudaFuncSetAttribute(k_attn_mma, cudaFuncAttributeMaxDynamicSharedMemorySize, AT_SMEM);
        inited = 1;
    }

    k_zero<<<16, 512>>>(out);                                  // launch 1
    k_wsum<<<64, 256>>>(Wq, Wk, Wv, bq, bk, bv);               // launch 2
    k_proj_mma<<<NROWS / 64, 256, PJ_SMEM>>>(inp, bq, bk);     // launch 3
    k_attn_mma<<<dim3(TT / 128, BB, 4), 128, AT_SMEM>>>();     // launch 4 (profiled)
    k_out2<<<dim3(64, BB), 128>>>(inp, out);                   // launch 5
}